// round 6
// baseline (speedup 1.0000x reference)
#include <cuda_runtime.h>
#include <cuda_fp16.h>
#include <cstdint>

// ============================================================================
// CATSCluster fused kernel — sm_103 baseline-PTX tensor path.
// Round-6: r3 geometry (128-row block, 1 CTA/SM, 64m x 64n warp tile, max B
// reuse) + r5 single-barrier direct-fp32 A fragments + distance-2 B prefetch
// + conflict-free A stride (272B = 68 words ≡ 4 mod 32).
//
//   X = X_data[:, 1:, :]  (16 x 4096 x 2304 fp32)
//   p1 = X[.., 768:1536] -> relu(relu(p1@W1^T)@W2^T) = Ha2   (128)
//   p2 = X[..,1536:2304] -> same weights             = Hb2
//   q  = X[..,   0: 768] -> relu(relu(q @W3^T)@W4^T) = Hq2
//   out = tanh(relu( (Hq2 * |Ha2-Hb2|) @ W5^T ))
// ============================================================================

// ---- smem layout (bytes), 128-row block ----
static constexpr int A32_STRIDE = 272;                  // 68 words ≡ 4 mod 32 -> conflict-free
static constexpr int A32_BYTES  = 128 * A32_STRIDE;     // 34816
static constexpr int SM_W5   = 0;                       // 512 B
static constexpr int SM_PART = 512;                     // float[128][2] = 1024
static constexpr int SM_A32  = 2048;                    // 2 x 34816
static constexpr int SM_H1   = SM_A32 + 2 * A32_BYTES;  // 128 x 528 = 67584
static constexpr int SM_D    = SM_H1 + 128 * 528;       // 128 x 272 = 34816
static constexpr int SMEM_BYTES = SM_D + 128 * 272;     // 174080

// Fragment-packed fp16 weights (prep kernel fills these every launch).
// L1: [chunk 12][n8-tile 32][k16 4][lane 32][4 halves]
// L2: [n8-tile 16][k16 16][lane 32][4 halves]
__device__ __half g_B1[2][12 * 32 * 4 * 32 * 4];   // W1, W3
__device__ __half g_B2[2][16 * 16 * 32 * 4];       // W2, W4

// ---------------------------------------------------------------- helpers
__device__ __forceinline__ uint32_t smem_u32(const void* p) {
    return (uint32_t)__cvta_generic_to_shared(p);
}
__device__ __forceinline__ void ldm_x4(uint32_t r[4], uint32_t addr) {
    asm volatile("ldmatrix.sync.aligned.m8n8.x4.shared.b16 {%0,%1,%2,%3}, [%4];"
                 : "=r"(r[0]), "=r"(r[1]), "=r"(r[2]), "=r"(r[3]) : "r"(addr));
}
__device__ __forceinline__ void mma16816(float c[4], const uint32_t a[4],
                                         uint32_t b0, uint32_t b1) {
    asm volatile(
        "mma.sync.aligned.m16n8k16.row.col.f32.f16.f16.f32 "
        "{%0,%1,%2,%3}, {%4,%5,%6,%7}, {%8,%9}, {%0,%1,%2,%3};"
        : "+f"(c[0]), "+f"(c[1]), "+f"(c[2]), "+f"(c[3])
        : "r"(a[0]), "r"(a[1]), "r"(a[2]), "r"(a[3]), "r"(b0), "r"(b1));
}
__device__ __forceinline__ void cp_async16(uint32_t saddr, const void* gaddr) {
    asm volatile("cp.async.cg.shared.global [%0], [%1], 16;"
                 :: "r"(saddr), "l"(gaddr) : "memory");
}
__device__ __forceinline__ void cp_commit() {
    asm volatile("cp.async.commit_group;" ::: "memory");
}
__device__ __forceinline__ void cp_wait0() {
    asm volatile("cp.async.wait_group 0;" ::: "memory");
}
__device__ __forceinline__ uint32_t h2u(__half2 h) {
    return *reinterpret_cast<uint32_t*>(&h);
}
// load float2 from smem, convert to packed f16x2
__device__ __forceinline__ uint32_t ldcvt(uint32_t saddr) {
    float x, y;
    asm("ld.shared.v2.f32 {%0,%1}, [%2];" : "=f"(x), "=f"(y) : "r"(saddr));
    return h2u(__floats2half2_rn(x, y));
}

// ------------------------------------------------- weight frag-pack kernel
__global__ void prep_kernel(const float* __restrict__ W1, const float* __restrict__ W2,
                            const float* __restrict__ W3, const float* __restrict__ W4) {
    int e = blockIdx.x * blockDim.x + threadIdx.x;    // 0 .. 196607
    {
        // L1 weights: W[n(256)][k(768)]
        int n = e / 768, k = e % 768;
        int kc = k >> 6;
        int j  = (k >> 4) & 3;
        int kl = k & 15;
        int p  = kl >> 3;
        int pos = kl & 7;
        int lane = (n & 7) * 4 + (pos >> 1);
        int h = pos & 1;
        int idx = ((((kc * 32 + (n >> 3)) * 4 + j) * 32 + lane) << 2) + p * 2 + h;
        g_B1[0][idx] = __float2half_rn(W1[e]);
        g_B1[1][idx] = __float2half_rn(W3[e]);
    }
    if (e < 128 * 256) {
        // L2 weights: W[n(128)][k(256)]
        int n = e / 256, k = e % 256;
        int j  = k >> 4;
        int kl = k & 15;
        int p  = kl >> 3;
        int pos = kl & 7;
        int lane = (n & 7) * 4 + (pos >> 1);
        int h = pos & 1;
        int idx = ((((n >> 3) * 16 + j) * 32 + lane) << 2) + p * 2 + h;
        g_B2[0][idx] = __float2half_rn(W2[e]);
        g_B2[1][idx] = __float2half_rn(W4[e]);
    }
}

// ----------------------------------------------------------------- main kernel
__global__ void __launch_bounds__(256, 1) fused_kernel(
    const float* __restrict__ X, const float* __restrict__ W5, float* __restrict__ out) {
    extern __shared__ __align__(128) char smem[];
    const uint32_t sb = smem_u32(smem);
    const int tid = threadIdx.x;
    const int w   = tid >> 5;
    const int l   = tid & 31;
    const int lq  = l & 3;

    const long long blk = blockIdx.x;                  // 512 blocks, 128 rows each
    const float* Xbase = X + ((blk >> 5) * 4097LL + (blk & 31) * 128LL + 1LL) * 2304LL;

    // chunk c (0..35): slice s=c/12, k-chunk kc=c%12, A32 buffer c&1.
    auto issue_chunk = [&](int c) {
        int ss = c / 12, kk = c % 12;
        int soff = (ss == 0) ? 768 : (ss == 1) ? 1536 : 0;   // p1, p2, q
        const int row = tid >> 1, seg = tid & 1;             // 2 threads/row, 128B each
        const float* src = Xbase + (long long)row * 2304 + soff + kk * 64 + seg * 32;
        uint32_t dst = sb + SM_A32 + (c & 1) * A32_BYTES + row * A32_STRIDE + seg * 128;
        #pragma unroll
        for (int i = 0; i < 8; i++)
            cp_async16(dst + i * 16, src + i * 4);
        cp_commit();
    };

    issue_chunk(0);
    if (tid < 128) ((float*)(smem + SM_W5))[tid] = W5[tid];

    // L1 warp tile: 64m x 64n (grid 2m x 4n).  L2 warp tile: 32m x 64n (4m x 2n).
    const int wm = w >> 2, wq = w & 3;
    const int wm2 = w >> 1, wn2 = w & 1;

    const float* W5s = (const float*)(smem + SM_W5);
    float* parts = (float*)(smem + SM_PART);

    // A fragment base: row = wm*64 + mf*16 + (l>>2) [+8], col = j*16 + lq*2 [+8]
    const uint32_t aFragBase = sb + SM_A32 + (wm * 64 + (l >> 2)) * A32_STRIDE + lq * 8;

    int c = 0;
    for (int s = 0; s < 3; s++) {
        const uint2* B1g = (const uint2*)g_B1[s == 2 ? 1 : 0];
        const uint2* B2g = (const uint2*)g_B2[s == 2 ? 1 : 0];

        // ================= layer 1: acc[4 mf][8 t][4] = Xslice @ W^T ============
        float acc[4][8][4];
        #pragma unroll
        for (int a = 0; a < 4; a++)
            #pragma unroll
            for (int b = 0; b < 8; b++)
                #pragma unroll
                for (int q = 0; q < 4; q++) acc[a][b][q] = 0.f;

        // distance-2 B pipeline: preload chunk0 j0 and j1 (overlaps wait+barrier)
        uint2 bv[2][8];
        {
            const uint2* bG0 = B1g + wq * 1024 + l;
            #pragma unroll
            for (int t = 0; t < 8; t++) {
                bv[0][t] = bG0[(t * 4 + 0) * 32];
                bv[1][t] = bG0[(t * 4 + 1) * 32];
            }
        }

        for (int kc = 0; kc < 12; kc++) {
            cp_wait0();
            __syncthreads();                 // chunk c staged & visible; other buf free
            if (c + 1 < 36) issue_chunk(c + 1);

            const uint32_t aB = aFragBase + (c & 1) * A32_BYTES;
            const uint2* bG  = B1g + kc * 4096 + wq * 1024 + l;
            const uint2* bGn = bG + 4096;    // next chunk (valid when kc<11)

            #pragma unroll
            for (int j = 0; j < 4; j++) {
                // A fragments straight from fp32 smem (conflict-free, stride 272)
                uint32_t afr[4][4];
                const uint32_t ra = aB + j * 64;            // j*16 cols * 4B
                #pragma unroll
                for (int mf = 0; mf < 4; mf++) {
                    const uint32_t rm = ra + mf * 16 * A32_STRIDE;
                    afr[mf][0] = ldcvt(rm);
                    afr[mf][1] = ldcvt(rm + 8 * A32_STRIDE);
                    afr[mf][2] = ldcvt(rm + 32);
                    afr[mf][3] = ldcvt(rm + 8 * A32_STRIDE + 32);
                }
                #pragma unroll
                for (int t = 0; t < 8; t++) {
                    uint32_t b0 = bv[j & 1][t].x, b1 = bv[j & 1][t].y;
                    // refill this slot at distance 2 (j+2, or next chunk's j0/j1)
                    if (j < 2)        bv[j & 1][t] = bG[(t * 4 + j + 2) * 32];
                    else if (kc < 11) bv[j & 1][t] = bGn[(t * 4 + (j - 2)) * 32];
                    mma16816(acc[0][t], afr[0], b0, b1);
                    mma16816(acc[1][t], afr[1], b0, b1);
                    mma16816(acc[2][t], afr[2], b0, b1);
                    mma16816(acc[3][t], afr[3], b0, b1);
                }
            }
            c++;
        }
        // (next slice's chunk 0 already in flight -> overlaps epilogue below)

        // ================= relu -> fp16 -> H1 smem (pad-528B rows) ==============
        #pragma unroll
        for (int mf = 0; mf < 4; mf++) {
            #pragma unroll
            for (int t = 0; t < 8; t++) {
                const int r0 = wm * 64 + mf * 16 + (l >> 2);
                const int col = wq * 64 + t * 8 + lq * 2;
                float* cc = acc[mf][t];
                *(uint32_t*)(smem + SM_H1 + r0 * 528 + col * 2) =
                    h2u(__floats2half2_rn(fmaxf(cc[0], 0.f), fmaxf(cc[1], 0.f)));
                *(uint32_t*)(smem + SM_H1 + (r0 + 8) * 528 + col * 2) =
                    h2u(__floats2half2_rn(fmaxf(cc[2], 0.f), fmaxf(cc[3], 0.f)));
            }
        }
        // preload L2-gemm B j0 (overlaps the barrier)
        uint2 bv2[8];
        {
            const uint2* bG = B2g + wn2 * 4096 + l;
            #pragma unroll
            for (int t = 0; t < 8; t++) bv2[t] = bG[(t * 16) * 32];
        }
        __syncthreads();

        // ================= layer 2: acc2[2 mf][8 t][4] = H1 @ W2^T ==============
        float acc2[2][8][4];
        #pragma unroll
        for (int a = 0; a < 2; a++)
            #pragma unroll
            for (int b = 0; b < 8; b++)
                #pragma unroll
                for (int q = 0; q < 4; q++) acc2[a][b][q] = 0.f;

        {
            const uint32_t aBase = sb + SM_H1 + (wm2 * 32 + (l & 15)) * 528 + (l >> 4) * 16;
            const uint2* bG = B2g + wn2 * 4096 + l;
            #pragma unroll
            for (int j = 0; j < 16; j++) {
                uint32_t afr[2][4];
                #pragma unroll
                for (int mf = 0; mf < 2; mf++)
                    ldm_x4(afr[mf], aBase + mf * 16 * 528 + j * 32);
                #pragma unroll
                for (int t = 0; t < 8; t++) {
                    uint32_t b0 = bv2[t].x, b1 = bv2[t].y;
                    if (j < 15) bv2[t] = bG[(t * 16 + j + 1) * 32];
                    mma16816(acc2[0][t], afr[0], b0, b1);
                    mma16816(acc2[1][t], afr[1], b0, b1);
                }
            }
        }
        // D-buffer accesses below are warp-private (same wm2/wn2 partition in all
        // slices); H1 is rewritten only after the next slice's chunk barriers.

        // ================= combine via D buffer (pad-272B rows, warp-private) ===
        if (s == 0) {
            #pragma unroll
            for (int mf = 0; mf < 2; mf++)
                #pragma unroll
                for (int t = 0; t < 8; t++) {
                    const int r0 = wm2 * 32 + mf * 16 + (l >> 2);
                    const int col = wn2 * 64 + t * 8 + lq * 2;
                    float* cc = acc2[mf][t];
                    *(uint32_t*)(smem + SM_D + r0 * 272 + col * 2) =
                        h2u(__floats2half2_rn(fmaxf(cc[0], 0.f), fmaxf(cc[1], 0.f)));
                    *(uint32_t*)(smem + SM_D + (r0 + 8) * 272 + col * 2) =
                        h2u(__floats2half2_rn(fmaxf(cc[2], 0.f), fmaxf(cc[3], 0.f)));
                }
        } else if (s == 1) {
            #pragma unroll
            for (int mf = 0; mf < 2; mf++)
                #pragma unroll
                for (int t = 0; t < 8; t++) {
                    const int r0 = wm2 * 32 + mf * 16 + (l >> 2);
                    const int col = wn2 * 64 + t * 8 + lq * 2;
                    float* cc = acc2[mf][t];
                    uint32_t* d0 = (uint32_t*)(smem + SM_D + r0 * 272 + col * 2);
                    uint32_t* d1 = (uint32_t*)(smem + SM_D + (r0 + 8) * 272 + col * 2);
                    float2 fa = __half22float2(*(__half2*)d0);
                    float2 fb = __half22float2(*(__half2*)d1);
                    *d0 = h2u(__floats2half2_rn(fabsf(fa.x - fmaxf(cc[0], 0.f)),
                                                fabsf(fa.y - fmaxf(cc[1], 0.f))));
                    *d1 = h2u(__floats2half2_rn(fabsf(fb.x - fmaxf(cc[2], 0.f)),
                                                fabsf(fb.y - fmaxf(cc[3], 0.f))));
                }
        } else {
            float pd[2][2] = {{0.f, 0.f}, {0.f, 0.f}};
            #pragma unroll
            for (int mf = 0; mf < 2; mf++)
                #pragma unroll
                for (int t = 0; t < 8; t++) {
                    const int r0 = wm2 * 32 + mf * 16 + (l >> 2);
                    const int col = wn2 * 64 + t * 8 + lq * 2;
                    float* cc = acc2[mf][t];
                    float2 da = __half22float2(*(__half2*)(smem + SM_D + r0 * 272 + col * 2));
                    float2 db = __half22float2(*(__half2*)(smem + SM_D + (r0 + 8) * 272 + col * 2));
                    float w0 = W5s[col], w1 = W5s[col + 1];
                    pd[mf][0] += w0 * fmaxf(cc[0], 0.f) * da.x + w1 * fmaxf(cc[1], 0.f) * da.y;
                    pd[mf][1] += w0 * fmaxf(cc[2], 0.f) * db.x + w1 * fmaxf(cc[3], 0.f) * db.y;
                }
            #pragma unroll
            for (int mf = 0; mf < 2; mf++)
                #pragma unroll
                for (int rr = 0; rr < 2; rr++) {
                    float v = pd[mf][rr];
                    v += __shfl_xor_sync(0xFFFFFFFF, v, 1);
                    v += __shfl_xor_sync(0xFFFFFFFF, v, 2);
                    if (lq == 0) {
                        int row = wm2 * 32 + mf * 16 + rr * 8 + (l >> 2);
                        parts[row * 2 + wn2] = v;
                    }
                }
        }
    }

    __syncthreads();
    if (tid < 128) {
        float sum = parts[tid * 2] + parts[tid * 2 + 1];
        out[blk * 128 + tid] = tanhf(fmaxf(sum, 0.f));
    }
}

// ------------------------------------------------------------------- launcher
extern "C" void kernel_launch(void* const* d_in, const int* in_sizes, int n_in,
                              void* d_out, int out_size) {
    const float* X  = (const float*)d_in[0];
    const float* W1 = (const float*)d_in[1];
    const float* W2 = (const float*)d_in[2];
    const float* W3 = (const float*)d_in[3];
    const float* W4 = (const float*)d_in[4];
    const float* W5 = (const float*)d_in[5];
    (void)in_sizes; (void)n_in; (void)out_size;

    cudaFuncSetAttribute(fused_kernel, cudaFuncAttributeMaxDynamicSharedMemorySize, SMEM_BYTES);

    prep_kernel<<<768, 256>>>(W1, W2, W3, W4);
    fused_kernel<<<512, 256, SMEM_BYTES>>>(X, W5, (float*)d_out);
}

// round 7
// speedup vs baseline: 1.2575x; 1.2575x over previous
#include <cuda_runtime.h>
#include <cuda_fp16.h>
#include <cstdint>

// ============================================================================
// CATSCluster fused kernel — sm_103 baseline-PTX tensor path.
// Round-7: 64-row blocks, 2 CTAs/SM, warp tile 64m x 32n (B-frag/MMA = 0.25,
// same as best round), ldmatrix A-feed from fp16 image, spill-free (<=128
// regs), in-place B prefetch.
//
//   X = X_data[:, 1:, :]  (16 x 4096 x 2304 fp32)
//   p1 = X[.., 768:1536] -> relu(relu(p1@W1^T)@W2^T) = Ha2   (128)
//   p2 = X[..,1536:2304] -> same weights             = Hb2
//   q  = X[..,   0: 768] -> relu(relu(q @W3^T)@W4^T) = Hq2
//   out = tanh(relu( (Hq2 * |Ha2-Hb2|) @ W5^T ))
// ============================================================================

// ---- smem layout (bytes), 64-row block ----
static constexpr int A32_STRIDE = 272;                  // 64 f32 + pad
static constexpr int A32_BYTES  = 64 * A32_STRIDE;      // 17408
static constexpr int SM_W5   = 0;                       // 512 B
static constexpr int SM_PART = 512;                     // float[64][8] = 2048
static constexpr int SM_A32  = 2560;                    // 2 x 17408
static constexpr int SM_AF16 = SM_A32 + 2 * A32_BYTES;  // 64 x 144 = 9216
static constexpr int SM_H1   = SM_AF16 + 64 * 144;      // 64 x 528 = 33792
static constexpr int SM_D    = SM_H1 + 64 * 528;        // 64 x 272 = 17408
static constexpr int SMEM_BYTES = SM_D + 64 * 272;      // 97792 -> 2 CTAs/SM

// Fragment-packed fp16 weights (prep kernel fills these every launch).
// L1: [chunk 12][n8-tile 32][k16 4][lane 32][4 halves]
// L2: [n8-tile 16][k16 16][lane 32][4 halves]
__device__ __half g_B1[2][12 * 32 * 4 * 32 * 4];   // W1, W3
__device__ __half g_B2[2][16 * 16 * 32 * 4];       // W2, W4

// ---------------------------------------------------------------- helpers
__device__ __forceinline__ uint32_t smem_u32(const void* p) {
    return (uint32_t)__cvta_generic_to_shared(p);
}
__device__ __forceinline__ void ldm_x4(uint32_t r[4], uint32_t addr) {
    asm volatile("ldmatrix.sync.aligned.m8n8.x4.shared.b16 {%0,%1,%2,%3}, [%4];"
                 : "=r"(r[0]), "=r"(r[1]), "=r"(r[2]), "=r"(r[3]) : "r"(addr));
}
__device__ __forceinline__ void mma16816(float c[4], const uint32_t a[4],
                                         uint32_t b0, uint32_t b1) {
    asm volatile(
        "mma.sync.aligned.m16n8k16.row.col.f32.f16.f16.f32 "
        "{%0,%1,%2,%3}, {%4,%5,%6,%7}, {%8,%9}, {%0,%1,%2,%3};"
        : "+f"(c[0]), "+f"(c[1]), "+f"(c[2]), "+f"(c[3])
        : "r"(a[0]), "r"(a[1]), "r"(a[2]), "r"(a[3]), "r"(b0), "r"(b1));
}
__device__ __forceinline__ void cp_async16(uint32_t saddr, const void* gaddr) {
    asm volatile("cp.async.cg.shared.global [%0], [%1], 16;"
                 :: "r"(saddr), "l"(gaddr) : "memory");
}
__device__ __forceinline__ void cp_commit() {
    asm volatile("cp.async.commit_group;" ::: "memory");
}
__device__ __forceinline__ void cp_wait0() {
    asm volatile("cp.async.wait_group 0;" ::: "memory");
}
__device__ __forceinline__ uint32_t h2u(__half2 h) {
    return *reinterpret_cast<uint32_t*>(&h);
}

// ------------------------------------------------- weight frag-pack kernel
__global__ void prep_kernel(const float* __restrict__ W1, const float* __restrict__ W2,
                            const float* __restrict__ W3, const float* __restrict__ W4) {
    int e = blockIdx.x * blockDim.x + threadIdx.x;    // 0 .. 196607
    {
        // L1 weights: W[n(256)][k(768)]
        int n = e / 768, k = e % 768;
        int kc = k >> 6;
        int j  = (k >> 4) & 3;
        int kl = k & 15;
        int p  = kl >> 3;
        int pos = kl & 7;
        int lane = (n & 7) * 4 + (pos >> 1);
        int h = pos & 1;
        int idx = ((((kc * 32 + (n >> 3)) * 4 + j) * 32 + lane) << 2) + p * 2 + h;
        g_B1[0][idx] = __float2half_rn(W1[e]);
        g_B1[1][idx] = __float2half_rn(W3[e]);
    }
    if (e < 128 * 256) {
        // L2 weights: W[n(128)][k(256)]
        int n = e / 256, k = e % 256;
        int j  = k >> 4;
        int kl = k & 15;
        int p  = kl >> 3;
        int pos = kl & 7;
        int lane = (n & 7) * 4 + (pos >> 1);
        int h = pos & 1;
        int idx = ((((n >> 3) * 16 + j) * 32 + lane) << 2) + p * 2 + h;
        g_B2[0][idx] = __float2half_rn(W2[e]);
        g_B2[1][idx] = __float2half_rn(W4[e]);
    }
}

// ----------------------------------------------------------------- main kernel
__global__ void __launch_bounds__(256, 2) fused_kernel(
    const float* __restrict__ X, const float* __restrict__ W5, float* __restrict__ out) {
    extern __shared__ __align__(128) char smem[];
    const uint32_t sb = smem_u32(smem);
    const int tid = threadIdx.x;
    const int w   = tid >> 5;           // warp 0..7
    const int l   = tid & 31;
    const int lq  = l & 3;

    const long long blk = blockIdx.x;                  // 1024 blocks, 64 rows each
    const float* Xbase = X + ((blk >> 6) * 4097LL + (blk & 63) * 64LL + 1LL) * 2304LL;

    // chunk c (0..35): slice s=c/12, k-chunk kc=c%12, A32 buffer c&1.
    auto issue_chunk = [&](int c) {
        int ss = c / 12, kk = c % 12;
        int soff = (ss == 0) ? 768 : (ss == 1) ? 1536 : 0;   // p1, p2, q
        const int row = tid >> 2, seg = tid & 3;             // 4 threads/row, 64B each
        const float* src = Xbase + (long long)row * 2304 + soff + kk * 64 + seg * 16;
        uint32_t dst = sb + SM_A32 + (c & 1) * A32_BYTES + row * A32_STRIDE + seg * 64;
        #pragma unroll
        for (int i = 0; i < 4; i++)
            cp_async16(dst + i * 16, src + i * 4);
        cp_commit();
    };

    issue_chunk(0);
    if (tid < 128) ((float*)(smem + SM_W5))[tid] = W5[tid];

    const float* W5s = (const float*)(smem + SM_W5);
    float* parts = (float*)(smem + SM_PART);

    // ldmatrix lane addressing (row within 16-tile = l&15, col-half = l>>4)
    const uint32_t aF16base = sb + SM_AF16 + (l & 15) * 144 + (l >> 4) * 16;
    const uint32_t h1base   = sb + SM_H1   + (l & 15) * 528 + (l >> 4) * 16;

    int c = 0;
    for (int s = 0; s < 3; s++) {
        // per-warp B bases: L1 warp covers n8-tiles w*4..w*4+3; L2 tiles w*2..w*2+1
        const uint2* B1g = (const uint2*)g_B1[s == 2 ? 1 : 0] + w * 512 + l;
        const uint2* B2g = (const uint2*)g_B2[s == 2 ? 1 : 0] + w * 1024 + l;

        // ================= layer 1: acc[4 mf][4 t][4] = Xslice @ W^T ============
        float acc[4][4][4];
        #pragma unroll
        for (int a = 0; a < 4; a++)
            #pragma unroll
            for (int b = 0; b < 4; b++)
                #pragma unroll
                for (int q = 0; q < 4; q++) acc[a][b][q] = 0.f;

        // preload chunk0 j0 B frags (overlaps cp wait + barrier)
        uint2 bv[4];
        #pragma unroll
        for (int t = 0; t < 4; t++) bv[t] = B1g[(t * 4) * 32];

        for (int kc = 0; kc < 12; kc++) {
            cp_wait0();
            __syncthreads();                 // chunk c staged; AF16 free; other buf free
            if (c + 1 < 36) issue_chunk(c + 1);

            // ---- convert fp32 chunk -> fp16 AF16 image (stride 144) ----
            {
                const int r = tid >> 2, seg = tid & 3;   // 16 f32 -> 16 f16 per thread
                const float4* src = (const float4*)(smem + SM_A32 + (c & 1) * A32_BYTES
                                                    + r * A32_STRIDE + seg * 64);
                uint32_t dst = sb + SM_AF16 + r * 144 + seg * 32;
                #pragma unroll
                for (int i = 0; i < 4; i++) {
                    float4 v = src[i];
                    uint32_t p0 = h2u(__floats2half2_rn(v.x, v.y));
                    uint32_t p1 = h2u(__floats2half2_rn(v.z, v.w));
                    asm volatile("st.shared.v2.b32 [%0], {%1,%2};"
                                 :: "r"(dst + i * 8), "r"(p0), "r"(p1));
                }
            }
            __syncthreads();

            const uint2* bG  = B1g + kc * 4096;
            const uint2* bGn = bG + 4096;    // next chunk (valid when kc<11)

            #pragma unroll
            for (int j = 0; j < 4; j++) {
                uint32_t afr[4][4];
                #pragma unroll
                for (int mf = 0; mf < 4; mf++)
                    ldm_x4(afr[mf], aF16base + mf * 16 * 144 + j * 32);
                #pragma unroll
                for (int t = 0; t < 4; t++) {
                    uint32_t b0 = bv[t].x, b1 = bv[t].y;
                    if (j < 3)        bv[t] = bG[(t * 4 + j + 1) * 32];
                    else if (kc < 11) bv[t] = bGn[(t * 4) * 32];
                    mma16816(acc[0][t], afr[0], b0, b1);
                    mma16816(acc[1][t], afr[1], b0, b1);
                    mma16816(acc[2][t], afr[2], b0, b1);
                    mma16816(acc[3][t], afr[3], b0, b1);
                }
            }
            c++;
        }
        // (next slice's chunk 0 already in flight -> overlaps epilogue below)

        // ================= relu -> fp16 -> H1 smem (stride 528) =================
        #pragma unroll
        for (int mf = 0; mf < 4; mf++) {
            #pragma unroll
            for (int t = 0; t < 4; t++) {
                const int r0 = mf * 16 + (l >> 2);
                const int col = w * 32 + t * 8 + lq * 2;
                float* cc = acc[mf][t];
                *(uint32_t*)(smem + SM_H1 + r0 * 528 + col * 2) =
                    h2u(__floats2half2_rn(fmaxf(cc[0], 0.f), fmaxf(cc[1], 0.f)));
                *(uint32_t*)(smem + SM_H1 + (r0 + 8) * 528 + col * 2) =
                    h2u(__floats2half2_rn(fmaxf(cc[2], 0.f), fmaxf(cc[3], 0.f)));
            }
        }
        // preload layer-2 B j0 (overlaps the barrier)
        uint2 bv2[2];
        #pragma unroll
        for (int t = 0; t < 2; t++) bv2[t] = B2g[(t * 16) * 32];
        __syncthreads();

        // ================= layer 2: acc2[4 mf][2 t][4] = H1 @ W2^T ==============
        float acc2[4][2][4];
        #pragma unroll
        for (int a = 0; a < 4; a++)
            #pragma unroll
            for (int b = 0; b < 2; b++)
                #pragma unroll
                for (int q = 0; q < 4; q++) acc2[a][b][q] = 0.f;

        #pragma unroll
        for (int j = 0; j < 16; j++) {
            uint32_t afr[4][4];
            #pragma unroll
            for (int mf = 0; mf < 4; mf++)
                ldm_x4(afr[mf], h1base + mf * 16 * 528 + j * 32);
            #pragma unroll
            for (int t = 0; t < 2; t++) {
                uint32_t b0 = bv2[t].x, b1 = bv2[t].y;
                if (j < 15) bv2[t] = B2g[(t * 16 + j + 1) * 32];
                mma16816(acc2[0][t], afr[0], b0, b1);
                mma16816(acc2[1][t], afr[1], b0, b1);
                mma16816(acc2[2][t], afr[2], b0, b1);
                mma16816(acc2[3][t], afr[3], b0, b1);
            }
        }
        // D-buffer accesses below: warp w owns cols [w*16, w*16+16) in all slices
        // -> no cross-warp race; H1 rewritten only after next slice's barriers.

        // ================= combine via D buffer (stride 272) ====================
        if (s == 0) {
            #pragma unroll
            for (int mf = 0; mf < 4; mf++)
                #pragma unroll
                for (int t = 0; t < 2; t++) {
                    const int r0 = mf * 16 + (l >> 2);
                    const int col = w * 16 + t * 8 + lq * 2;
                    float* cc = acc2[mf][t];
                    *(uint32_t*)(smem + SM_D + r0 * 272 + col * 2) =
                        h2u(__floats2half2_rn(fmaxf(cc[0], 0.f), fmaxf(cc[1], 0.f)));
                    *(uint32_t*)(smem + SM_D + (r0 + 8) * 272 + col * 2) =
                        h2u(__floats2half2_rn(fmaxf(cc[2], 0.f), fmaxf(cc[3], 0.f)));
                }
        } else if (s == 1) {
            #pragma unroll
            for (int mf = 0; mf < 4; mf++)
                #pragma unroll
                for (int t = 0; t < 2; t++) {
                    const int r0 = mf * 16 + (l >> 2);
                    const int col = w * 16 + t * 8 + lq * 2;
                    float* cc = acc2[mf][t];
                    uint32_t* d0 = (uint32_t*)(smem + SM_D + r0 * 272 + col * 2);
                    uint32_t* d1 = (uint32_t*)(smem + SM_D + (r0 + 8) * 272 + col * 2);
                    float2 fa = __half22float2(*(__half2*)d0);
                    float2 fb = __half22float2(*(__half2*)d1);
                    *d0 = h2u(__floats2half2_rn(fabsf(fa.x - fmaxf(cc[0], 0.f)),
                                                fabsf(fa.y - fmaxf(cc[1], 0.f))));
                    *d1 = h2u(__floats2half2_rn(fabsf(fb.x - fmaxf(cc[2], 0.f)),
                                                fabsf(fb.y - fmaxf(cc[3], 0.f))));
                }
        } else {
            // s==2: pd[mf][rr] = per-row partial over this warp's 16 cols
            float pd[4][2];
            #pragma unroll
            for (int mf = 0; mf < 4; mf++) { pd[mf][0] = 0.f; pd[mf][1] = 0.f; }
            #pragma unroll
            for (int mf = 0; mf < 4; mf++)
                #pragma unroll
                for (int t = 0; t < 2; t++) {
                    const int r0 = mf * 16 + (l >> 2);
                    const int col = w * 16 + t * 8 + lq * 2;
                    float* cc = acc2[mf][t];
                    float2 da = __half22float2(*(__half2*)(smem + SM_D + r0 * 272 + col * 2));
                    float2 db = __half22float2(*(__half2*)(smem + SM_D + (r0 + 8) * 272 + col * 2));
                    float w0 = W5s[col], w1 = W5s[col + 1];
                    pd[mf][0] += w0 * fmaxf(cc[0], 0.f) * da.x + w1 * fmaxf(cc[1], 0.f) * da.y;
                    pd[mf][1] += w0 * fmaxf(cc[2], 0.f) * db.x + w1 * fmaxf(cc[3], 0.f) * db.y;
                }
            #pragma unroll
            for (int mf = 0; mf < 4; mf++)
                #pragma unroll
                for (int rr = 0; rr < 2; rr++) {
                    float v = pd[mf][rr];
                    v += __shfl_xor_sync(0xFFFFFFFF, v, 1);
                    v += __shfl_xor_sync(0xFFFFFFFF, v, 2);
                    if (lq == 0) {
                        int row = mf * 16 + rr * 8 + (l >> 2);
                        parts[row * 8 + w] = v;      // warp w's 16-col partial
                    }
                }
        }
    }

    __syncthreads();
    if (tid < 64) {
        const float* p = parts + tid * 8;
        float sum = ((p[0] + p[1]) + (p[2] + p[3])) + ((p[4] + p[5]) + (p[6] + p[7]));
        out[blk * 64 + tid] = tanhf(fmaxf(sum, 0.f));
    }
}

// ------------------------------------------------------------------- launcher
extern "C" void kernel_launch(void* const* d_in, const int* in_sizes, int n_in,
                              void* d_out, int out_size) {
    const float* X  = (const float*)d_in[0];
    const float* W1 = (const float*)d_in[1];
    const float* W2 = (const float*)d_in[2];
    const float* W3 = (const float*)d_in[3];
    const float* W4 = (const float*)d_in[4];
    const float* W5 = (const float*)d_in[5];
    (void)in_sizes; (void)n_in; (void)out_size;

    cudaFuncSetAttribute(fused_kernel, cudaFuncAttributeMaxDynamicSharedMemorySize, SMEM_BYTES);

    prep_kernel<<<768, 256>>>(W1, W2, W3, W4);
    fused_kernel<<<1024, 256, SMEM_BYTES>>>(X, W5, (float*)d_out);
}

// round 8
// speedup vs baseline: 1.3359x; 1.0624x over previous
#include <cuda_runtime.h>
#include <cuda_fp16.h>
#include <cstdint>

// ============================================================================
// CATSCluster fused kernel — sm_103 baseline-PTX tensor path.
// Round-8: r7 geometry (64-row block, 2 CTAs/SM, warp tile 64m x 32n,
// ldmatrix feed, spill-free) + register-resident X prefetch:
//   LDG chunk c+1 into 4 x float4 regs during chunk c's MMAs, convert
//   in-register -> STS fp16 into a double-buffered AF16 image.
//   -> no fp32 smem staging, ONE barrier per chunk, ~60% less A-path L1 traffic.
//
//   X = X_data[:, 1:, :]  (16 x 4096 x 2304 fp32)
//   p1 = X[.., 768:1536] -> relu(relu(p1@W1^T)@W2^T) = Ha2   (128)
//   p2 = X[..,1536:2304] -> same weights             = Hb2
//   q  = X[..,   0: 768] -> relu(relu(q @W3^T)@W4^T) = Hq2
//   out = tanh(relu( (Hq2 * |Ha2-Hb2|) @ W5^T ))
// ============================================================================

// ---- smem layout (bytes), 64-row block ----
static constexpr int AF16_STRIDE = 144;                   // 64 f16 + 16B pad
static constexpr int AF16_BYTES  = 64 * AF16_STRIDE;      // 9216
static constexpr int SM_W5   = 0;                         // 512 B
static constexpr int SM_PART = 512;                       // float[64][8] = 2048
static constexpr int SM_AF16 = 2560;                      // 2 x 9216 (double buffer)
static constexpr int SM_H1   = SM_AF16 + 2 * AF16_BYTES;  // 64 x 528 = 33792
static constexpr int SM_D    = SM_H1 + 64 * 528;          // 64 x 272 = 17408
static constexpr int SMEM_BYTES = SM_D + 64 * 272;        // 74368 -> 2 CTAs/SM

// Fragment-packed fp16 weights (prep kernel fills these every launch).
// L1: [chunk 12][n8-tile 32][k16 4][lane 32][4 halves]
// L2: [n8-tile 16][k16 16][lane 32][4 halves]
__device__ __half g_B1[2][12 * 32 * 4 * 32 * 4];   // W1, W3
__device__ __half g_B2[2][16 * 16 * 32 * 4];       // W2, W4

// ---------------------------------------------------------------- helpers
__device__ __forceinline__ uint32_t smem_u32(const void* p) {
    return (uint32_t)__cvta_generic_to_shared(p);
}
__device__ __forceinline__ void ldm_x4(uint32_t r[4], uint32_t addr) {
    asm volatile("ldmatrix.sync.aligned.m8n8.x4.shared.b16 {%0,%1,%2,%3}, [%4];"
                 : "=r"(r[0]), "=r"(r[1]), "=r"(r[2]), "=r"(r[3]) : "r"(addr));
}
__device__ __forceinline__ void mma16816(float c[4], const uint32_t a[4],
                                         uint32_t b0, uint32_t b1) {
    asm volatile(
        "mma.sync.aligned.m16n8k16.row.col.f32.f16.f16.f32 "
        "{%0,%1,%2,%3}, {%4,%5,%6,%7}, {%8,%9}, {%0,%1,%2,%3};"
        : "+f"(c[0]), "+f"(c[1]), "+f"(c[2]), "+f"(c[3])
        : "r"(a[0]), "r"(a[1]), "r"(a[2]), "r"(a[3]), "r"(b0), "r"(b1));
}
__device__ __forceinline__ uint32_t h2u(__half2 h) {
    return *reinterpret_cast<uint32_t*>(&h);
}

// ------------------------------------------------- weight frag-pack kernel
__global__ void prep_kernel(const float* __restrict__ W1, const float* __restrict__ W2,
                            const float* __restrict__ W3, const float* __restrict__ W4) {
    int e = blockIdx.x * blockDim.x + threadIdx.x;    // 0 .. 196607
    {
        // L1 weights: W[n(256)][k(768)]
        int n = e / 768, k = e % 768;
        int kc = k >> 6;
        int j  = (k >> 4) & 3;
        int kl = k & 15;
        int p  = kl >> 3;
        int pos = kl & 7;
        int lane = (n & 7) * 4 + (pos >> 1);
        int h = pos & 1;
        int idx = ((((kc * 32 + (n >> 3)) * 4 + j) * 32 + lane) << 2) + p * 2 + h;
        g_B1[0][idx] = __float2half_rn(W1[e]);
        g_B1[1][idx] = __float2half_rn(W3[e]);
    }
    if (e < 128 * 256) {
        // L2 weights: W[n(128)][k(256)]
        int n = e / 256, k = e % 256;
        int j  = k >> 4;
        int kl = k & 15;
        int p  = kl >> 3;
        int pos = kl & 7;
        int lane = (n & 7) * 4 + (pos >> 1);
        int h = pos & 1;
        int idx = ((((n >> 3) * 16 + j) * 32 + lane) << 2) + p * 2 + h;
        g_B2[0][idx] = __float2half_rn(W2[e]);
        g_B2[1][idx] = __float2half_rn(W4[e]);
    }
}

// ----------------------------------------------------------------- main kernel
__global__ void __launch_bounds__(256, 2) fused_kernel(
    const float* __restrict__ X, const float* __restrict__ W5, float* __restrict__ out) {
    extern __shared__ __align__(128) char smem[];
    const uint32_t sb = smem_u32(smem);
    const int tid = threadIdx.x;
    const int w   = tid >> 5;           // warp 0..7
    const int l   = tid & 31;
    const int lq  = l & 3;

    const long long blk = blockIdx.x;                  // 1024 blocks, 64 rows each
    const float* Xbase = X + ((blk >> 6) * 4097LL + (blk & 63) * 64LL + 1LL) * 2304LL;

    // X prefetch assignment: 4 threads/row, 16 floats (64B) each
    const int xrow = tid >> 2, xseg = tid & 3;
    const float* xsrc_row = Xbase + (long long)xrow * 2304 + xseg * 16;

    // chunk c (0..35): slice s=c/12, k-chunk kc=c%12, AF16 buffer c&1.
    float4 xv0, xv1, xv2, xv3;
    auto ldg_chunk = [&](int c) {
        int ss = c / 12, kk = c % 12;
        int soff = (ss == 0) ? 768 : (ss == 1) ? 1536 : 0;   // p1, p2, q
        const float4* src = (const float4*)(xsrc_row + soff + kk * 64);
        xv0 = src[0]; xv1 = src[1]; xv2 = src[2]; xv3 = src[3];
    };
    // this thread's STS target within an AF16 buffer (32B fp16 for its 16 floats)
    const uint32_t xdst = sb + SM_AF16 + xrow * AF16_STRIDE + xseg * 32;

    ldg_chunk(0);
    if (tid < 128) ((float*)(smem + SM_W5))[tid] = W5[tid];

    const float* W5s = (const float*)(smem + SM_W5);
    float* parts = (float*)(smem + SM_PART);

    // ldmatrix lane addressing (row within 16-tile = l&15, col-half = l>>4)
    const uint32_t aF16lane = sb + SM_AF16 + (l & 15) * AF16_STRIDE + (l >> 4) * 16;
    const uint32_t h1base   = sb + SM_H1   + (l & 15) * 528 + (l >> 4) * 16;

    int c = 0;
    for (int s = 0; s < 3; s++) {
        // per-warp B bases: L1 warp covers n8-tiles w*4..w*4+3; L2 tiles w*2..w*2+1
        const uint2* B1g = (const uint2*)g_B1[s == 2 ? 1 : 0] + w * 512 + l;
        const uint2* B2g = (const uint2*)g_B2[s == 2 ? 1 : 0] + w * 1024 + l;

        // ================= layer 1: acc[4 mf][4 t][4] = Xslice @ W^T ============
        float acc[4][4][4];
        #pragma unroll
        for (int a = 0; a < 4; a++)
            #pragma unroll
            for (int b = 0; b < 4; b++)
                #pragma unroll
                for (int q = 0; q < 4; q++) acc[a][b][q] = 0.f;

        // preload chunk0 j0 B frags (overlaps the first barrier)
        uint2 bv[4];
        #pragma unroll
        for (int t = 0; t < 4; t++) bv[t] = B1g[(t * 4) * 32];

        #pragma unroll 1
        for (int kc = 0; kc < 12; kc++) {
            // ---- convert register X -> fp16 AF16[c&1] (32B STS) ----
            {
                uint32_t dst = xdst + (c & 1) * AF16_BYTES;
                uint32_t p0 = h2u(__floats2half2_rn(xv0.x, xv0.y));
                uint32_t p1 = h2u(__floats2half2_rn(xv0.z, xv0.w));
                uint32_t p2 = h2u(__floats2half2_rn(xv1.x, xv1.y));
                uint32_t p3 = h2u(__floats2half2_rn(xv1.z, xv1.w));
                asm volatile("st.shared.v4.b32 [%0], {%1,%2,%3,%4};"
                             :: "r"(dst), "r"(p0), "r"(p1), "r"(p2), "r"(p3));
                uint32_t p4 = h2u(__floats2half2_rn(xv2.x, xv2.y));
                uint32_t p5 = h2u(__floats2half2_rn(xv2.z, xv2.w));
                uint32_t p6 = h2u(__floats2half2_rn(xv3.x, xv3.y));
                uint32_t p7 = h2u(__floats2half2_rn(xv3.z, xv3.w));
                asm volatile("st.shared.v4.b32 [%0], {%1,%2,%3,%4};"
                             :: "r"(dst + 16), "r"(p4), "r"(p5), "r"(p6), "r"(p7));
            }
            __syncthreads();                 // AF16[c&1] complete; (see proof in notes:
                                             // barrier(c-1) ordered all MMA(c-2) readers
                                             // of this buffer before any STS here)
            if (c + 1 < 36) ldg_chunk(c + 1);    // LDG hidden behind this chunk's MMAs

            const uint32_t aB = aF16lane + (c & 1) * AF16_BYTES;
            const uint2* bG  = B1g + (c % 12) * 4096;
            const uint2* bGn = bG + 4096;    // next chunk (valid when kc<11)

            #pragma unroll
            for (int j = 0; j < 4; j++) {
                uint32_t afr[4][4];
                #pragma unroll
                for (int mf = 0; mf < 4; mf++)
                    ldm_x4(afr[mf], aB + mf * 16 * AF16_STRIDE + j * 32);
                #pragma unroll
                for (int t = 0; t < 4; t++) {
                    uint32_t b0 = bv[t].x, b1 = bv[t].y;
                    if (j < 3)        bv[t] = bG[(t * 4 + j + 1) * 32];
                    else if (kc < 11) bv[t] = bGn[(t * 4) * 32];
                    mma16816(acc[0][t], afr[0], b0, b1);
                    mma16816(acc[1][t], afr[1], b0, b1);
                    mma16816(acc[2][t], afr[2], b0, b1);
                    mma16816(acc[3][t], afr[3], b0, b1);
                }
            }
            c++;
        }
        // (next slice's chunk 0 X already in registers -> epilogue overlaps nothing
        //  memory-bound; B2 j0 preload below covers the L2 latency)

        // ================= relu -> fp16 -> H1 smem (stride 528) =================
        #pragma unroll
        for (int mf = 0; mf < 4; mf++) {
            #pragma unroll
            for (int t = 0; t < 4; t++) {
                const int r0 = mf * 16 + (l >> 2);
                const int col = w * 32 + t * 8 + lq * 2;
                float* cc = acc[mf][t];
                *(uint32_t*)(smem + SM_H1 + r0 * 528 + col * 2) =
                    h2u(__floats2half2_rn(fmaxf(cc[0], 0.f), fmaxf(cc[1], 0.f)));
                *(uint32_t*)(smem + SM_H1 + (r0 + 8) * 528 + col * 2) =
                    h2u(__floats2half2_rn(fmaxf(cc[2], 0.f), fmaxf(cc[3], 0.f)));
            }
        }
        // preload layer-2 B j0 (overlaps the barrier)
        uint2 bv2[2];
        #pragma unroll
        for (int t = 0; t < 2; t++) bv2[t] = B2g[(t * 16) * 32];
        __syncthreads();

        // ================= layer 2: acc2[4 mf][2 t][4] = H1 @ W2^T ==============
        float acc2[4][2][4];
        #pragma unroll
        for (int a = 0; a < 4; a++)
            #pragma unroll
            for (int b = 0; b < 2; b++)
                #pragma unroll
                for (int q = 0; q < 4; q++) acc2[a][b][q] = 0.f;

        #pragma unroll
        for (int j = 0; j < 16; j++) {
            uint32_t afr[4][4];
            #pragma unroll
            for (int mf = 0; mf < 4; mf++)
                ldm_x4(afr[mf], h1base + mf * 16 * 528 + j * 32);
            #pragma unroll
            for (int t = 0; t < 2; t++) {
                uint32_t b0 = bv2[t].x, b1 = bv2[t].y;
                if (j < 15) bv2[t] = B2g[(t * 16 + j + 1) * 32];
                mma16816(acc2[0][t], afr[0], b0, b1);
                mma16816(acc2[1][t], afr[1], b0, b1);
                mma16816(acc2[2][t], afr[2], b0, b1);
                mma16816(acc2[3][t], afr[3], b0, b1);
            }
        }
        // D-buffer accesses below: warp w owns cols [w*16, w*16+16) in all slices
        // -> no cross-warp race; H1 rewritten only after next slice's barriers.

        // ================= combine via D buffer (stride 272) ====================
        if (s == 0) {
            #pragma unroll
            for (int mf = 0; mf < 4; mf++)
                #pragma unroll
                for (int t = 0; t < 2; t++) {
                    const int r0 = mf * 16 + (l >> 2);
                    const int col = w * 16 + t * 8 + lq * 2;
                    float* cc = acc2[mf][t];
                    *(uint32_t*)(smem + SM_D + r0 * 272 + col * 2) =
                        h2u(__floats2half2_rn(fmaxf(cc[0], 0.f), fmaxf(cc[1], 0.f)));
                    *(uint32_t*)(smem + SM_D + (r0 + 8) * 272 + col * 2) =
                        h2u(__floats2half2_rn(fmaxf(cc[2], 0.f), fmaxf(cc[3], 0.f)));
                }
        } else if (s == 1) {
            #pragma unroll
            for (int mf = 0; mf < 4; mf++)
                #pragma unroll
                for (int t = 0; t < 2; t++) {
                    const int r0 = mf * 16 + (l >> 2);
                    const int col = w * 16 + t * 8 + lq * 2;
                    float* cc = acc2[mf][t];
                    uint32_t* d0 = (uint32_t*)(smem + SM_D + r0 * 272 + col * 2);
                    uint32_t* d1 = (uint32_t*)(smem + SM_D + (r0 + 8) * 272 + col * 2);
                    float2 fa = __half22float2(*(__half2*)d0);
                    float2 fb = __half22float2(*(__half2*)d1);
                    *d0 = h2u(__floats2half2_rn(fabsf(fa.x - fmaxf(cc[0], 0.f)),
                                                fabsf(fa.y - fmaxf(cc[1], 0.f))));
                    *d1 = h2u(__floats2half2_rn(fabsf(fb.x - fmaxf(cc[2], 0.f)),
                                                fabsf(fb.y - fmaxf(cc[3], 0.f))));
                }
        } else {
            // s==2: pd[mf][rr] = per-row partial over this warp's 16 cols
            float pd[4][2];
            #pragma unroll
            for (int mf = 0; mf < 4; mf++) { pd[mf][0] = 0.f; pd[mf][1] = 0.f; }
            #pragma unroll
            for (int mf = 0; mf < 4; mf++)
                #pragma unroll
                for (int t = 0; t < 2; t++) {
                    const int r0 = mf * 16 + (l >> 2);
                    const int col = w * 16 + t * 8 + lq * 2;
                    float* cc = acc2[mf][t];
                    float2 da = __half22float2(*(__half2*)(smem + SM_D + r0 * 272 + col * 2));
                    float2 db = __half22float2(*(__half2*)(smem + SM_D + (r0 + 8) * 272 + col * 2));
                    float w0 = W5s[col], w1 = W5s[col + 1];
                    pd[mf][0] += w0 * fmaxf(cc[0], 0.f) * da.x + w1 * fmaxf(cc[1], 0.f) * da.y;
                    pd[mf][1] += w0 * fmaxf(cc[2], 0.f) * db.x + w1 * fmaxf(cc[3], 0.f) * db.y;
                }
            #pragma unroll
            for (int mf = 0; mf < 4; mf++)
                #pragma unroll
                for (int rr = 0; rr < 2; rr++) {
                    float v = pd[mf][rr];
                    v += __shfl_xor_sync(0xFFFFFFFF, v, 1);
                    v += __shfl_xor_sync(0xFFFFFFFF, v, 2);
                    if (lq == 0) {
                        int row = mf * 16 + rr * 8 + (l >> 2);
                        parts[row * 8 + w] = v;      // warp w's 16-col partial
                    }
                }
        }
    }

    __syncthreads();
    if (tid < 64) {
        const float* p = parts + tid * 8;
        float sum = ((p[0] + p[1]) + (p[2] + p[3])) + ((p[4] + p[5]) + (p[6] + p[7]));
        out[blk * 64 + tid] = tanhf(fmaxf(sum, 0.f));
    }
}

// ------------------------------------------------------------------- launcher
extern "C" void kernel_launch(void* const* d_in, const int* in_sizes, int n_in,
                              void* d_out, int out_size) {
    const float* X  = (const float*)d_in[0];
    const float* W1 = (const float*)d_in[1];
    const float* W2 = (const float*)d_in[2];
    const float* W3 = (const float*)d_in[3];
    const float* W4 = (const float*)d_in[4];
    const float* W5 = (const float*)d_in[5];
    (void)in_sizes; (void)n_in; (void)out_size;

    cudaFuncSetAttribute(fused_kernel, cudaFuncAttributeMaxDynamicSharedMemorySize, SMEM_BYTES);

    prep_kernel<<<768, 256>>>(W1, W2, W3, W4);
    fused_kernel<<<1024, 256, SMEM_BYTES>>>(X, W5, (float*)d_out);
}

// round 9
// speedup vs baseline: 1.4183x; 1.0617x over previous
#include <cuda_runtime.h>
#include <cuda_fp16.h>
#include <cstdint>

// ============================================================================
// CATSCluster fused kernel — sm_103 baseline-PTX tensor path.
// Round-9: r8 (64-row block, 2 CTAs/SM, warp tile 64m x 32n, register-X
// prefetch, one barrier/chunk) + DISTANCE-2 B prefetch in both GEMMs:
// B frags are consumed ~2 j-steps (>=200 cyc) after their LDG issues, covering
// the 234-262 cyc L2 hit latency that distance-1 exposed.
//
//   X = X_data[:, 1:, :]  (16 x 4096 x 2304 fp32)
//   p1 = X[.., 768:1536] -> relu(relu(p1@W1^T)@W2^T) = Ha2   (128)
//   p2 = X[..,1536:2304] -> same weights             = Hb2
//   q  = X[..,   0: 768] -> relu(relu(q @W3^T)@W4^T) = Hq2
//   out = tanh(relu( (Hq2 * |Ha2-Hb2|) @ W5^T ))
// ============================================================================

// ---- smem layout (bytes), 64-row block ----
static constexpr int AF16_STRIDE = 144;                   // 64 f16 + 16B pad
static constexpr int AF16_BYTES  = 64 * AF16_STRIDE;      // 9216
static constexpr int SM_W5   = 0;                         // 512 B
static constexpr int SM_PART = 512;                       // float[64][8] = 2048
static constexpr int SM_AF16 = 2560;                      // 2 x 9216 (double buffer)
static constexpr int SM_H1   = SM_AF16 + 2 * AF16_BYTES;  // 64 x 528 = 33792
static constexpr int SM_D    = SM_H1 + 64 * 528;          // 64 x 272 = 17408
static constexpr int SMEM_BYTES = SM_D + 64 * 272;        // 74368 -> 2 CTAs/SM

// Fragment-packed fp16 weights (prep kernel fills these every launch).
// L1: [chunk 12][n8-tile 32][k16 4][lane 32][4 halves]
// L2: [n8-tile 16][k16 16][lane 32][4 halves]
__device__ __half g_B1[2][12 * 32 * 4 * 32 * 4];   // W1, W3
__device__ __half g_B2[2][16 * 16 * 32 * 4];       // W2, W4

// ---------------------------------------------------------------- helpers
__device__ __forceinline__ uint32_t smem_u32(const void* p) {
    return (uint32_t)__cvta_generic_to_shared(p);
}
__device__ __forceinline__ void ldm_x4(uint32_t r[4], uint32_t addr) {
    asm volatile("ldmatrix.sync.aligned.m8n8.x4.shared.b16 {%0,%1,%2,%3}, [%4];"
                 : "=r"(r[0]), "=r"(r[1]), "=r"(r[2]), "=r"(r[3]) : "r"(addr));
}
__device__ __forceinline__ void mma16816(float c[4], const uint32_t a[4],
                                         uint32_t b0, uint32_t b1) {
    asm volatile(
        "mma.sync.aligned.m16n8k16.row.col.f32.f16.f16.f32 "
        "{%0,%1,%2,%3}, {%4,%5,%6,%7}, {%8,%9}, {%0,%1,%2,%3};"
        : "+f"(c[0]), "+f"(c[1]), "+f"(c[2]), "+f"(c[3])
        : "r"(a[0]), "r"(a[1]), "r"(a[2]), "r"(a[3]), "r"(b0), "r"(b1));
}
__device__ __forceinline__ uint32_t h2u(__half2 h) {
    return *reinterpret_cast<uint32_t*>(&h);
}

// ------------------------------------------------- weight frag-pack kernel
__global__ void prep_kernel(const float* __restrict__ W1, const float* __restrict__ W2,
                            const float* __restrict__ W3, const float* __restrict__ W4) {
    int e = blockIdx.x * blockDim.x + threadIdx.x;    // 0 .. 196607
    {
        // L1 weights: W[n(256)][k(768)]
        int n = e / 768, k = e % 768;
        int kc = k >> 6;
        int j  = (k >> 4) & 3;
        int kl = k & 15;
        int p  = kl >> 3;
        int pos = kl & 7;
        int lane = (n & 7) * 4 + (pos >> 1);
        int h = pos & 1;
        int idx = ((((kc * 32 + (n >> 3)) * 4 + j) * 32 + lane) << 2) + p * 2 + h;
        g_B1[0][idx] = __float2half_rn(W1[e]);
        g_B1[1][idx] = __float2half_rn(W3[e]);
    }
    if (e < 128 * 256) {
        // L2 weights: W[n(128)][k(256)]
        int n = e / 256, k = e % 256;
        int j  = k >> 4;
        int kl = k & 15;
        int p  = kl >> 3;
        int pos = kl & 7;
        int lane = (n & 7) * 4 + (pos >> 1);
        int h = pos & 1;
        int idx = ((((n >> 3) * 16 + j) * 32 + lane) << 2) + p * 2 + h;
        g_B2[0][idx] = __float2half_rn(W2[e]);
        g_B2[1][idx] = __float2half_rn(W4[e]);
    }
}

// ----------------------------------------------------------------- main kernel
__global__ void __launch_bounds__(256, 2) fused_kernel(
    const float* __restrict__ X, const float* __restrict__ W5, float* __restrict__ out) {
    extern __shared__ __align__(128) char smem[];
    const uint32_t sb = smem_u32(smem);
    const int tid = threadIdx.x;
    const int w   = tid >> 5;           // warp 0..7
    const int l   = tid & 31;
    const int lq  = l & 3;

    const long long blk = blockIdx.x;                  // 1024 blocks, 64 rows each
    const float* Xbase = X + ((blk >> 6) * 4097LL + (blk & 63) * 64LL + 1LL) * 2304LL;

    // X prefetch assignment: 4 threads/row, 16 floats (64B) each
    const int xrow = tid >> 2, xseg = tid & 3;
    const float* xsrc_row = Xbase + (long long)xrow * 2304 + xseg * 16;

    // chunk c (0..35): slice s=c/12, k-chunk kc=c%12, AF16 buffer c&1.
    float4 xv0, xv1, xv2, xv3;
    auto ldg_chunk = [&](int c) {
        int ss = c / 12, kk = c % 12;
        int soff = (ss == 0) ? 768 : (ss == 1) ? 1536 : 0;   // p1, p2, q
        const float4* src = (const float4*)(xsrc_row + soff + kk * 64);
        xv0 = src[0]; xv1 = src[1]; xv2 = src[2]; xv3 = src[3];
    };
    // this thread's STS target within an AF16 buffer (32B fp16 for its 16 floats)
    const uint32_t xdst = sb + SM_AF16 + xrow * AF16_STRIDE + xseg * 32;

    ldg_chunk(0);
    if (tid < 128) ((float*)(smem + SM_W5))[tid] = W5[tid];

    const float* W5s = (const float*)(smem + SM_W5);
    float* parts = (float*)(smem + SM_PART);

    // ldmatrix lane addressing (row within 16-tile = l&15, col-half = l>>4)
    const uint32_t aF16lane = sb + SM_AF16 + (l & 15) * AF16_STRIDE + (l >> 4) * 16;
    const uint32_t h1base   = sb + SM_H1   + (l & 15) * 528 + (l >> 4) * 16;

    int c = 0;
    for (int s = 0; s < 3; s++) {
        // per-warp B bases: L1 warp covers n8-tiles w*4..w*4+3; L2 tiles w*2..w*2+1
        const uint2* B1g = (const uint2*)g_B1[s == 2 ? 1 : 0] + w * 512 + l;
        const uint2* B2g = (const uint2*)g_B2[s == 2 ? 1 : 0] + w * 1024 + l;

        // ================= layer 1: acc[4 mf][4 t][4] = Xslice @ W^T ============
        float acc[4][4][4];
        #pragma unroll
        for (int a = 0; a < 4; a++)
            #pragma unroll
            for (int b = 0; b < 4; b++)
                #pragma unroll
                for (int q = 0; q < 4; q++) acc[a][b][q] = 0.f;

        // distance-2 B ring: preload chunk0 j0 AND j1 (overlap the first barrier)
        uint2 bv[2][4];
        #pragma unroll
        for (int t = 0; t < 4; t++) {
            bv[0][t] = B1g[(t * 4 + 0) * 32];
            bv[1][t] = B1g[(t * 4 + 1) * 32];
        }

        #pragma unroll 1
        for (int kc = 0; kc < 12; kc++) {
            // ---- convert register X -> fp16 AF16[c&1] (32B STS) ----
            {
                uint32_t dst = xdst + (c & 1) * AF16_BYTES;
                uint32_t p0 = h2u(__floats2half2_rn(xv0.x, xv0.y));
                uint32_t p1 = h2u(__floats2half2_rn(xv0.z, xv0.w));
                uint32_t p2 = h2u(__floats2half2_rn(xv1.x, xv1.y));
                uint32_t p3 = h2u(__floats2half2_rn(xv1.z, xv1.w));
                asm volatile("st.shared.v4.b32 [%0], {%1,%2,%3,%4};"
                             :: "r"(dst), "r"(p0), "r"(p1), "r"(p2), "r"(p3));
                uint32_t p4 = h2u(__floats2half2_rn(xv2.x, xv2.y));
                uint32_t p5 = h2u(__floats2half2_rn(xv2.z, xv2.w));
                uint32_t p6 = h2u(__floats2half2_rn(xv3.x, xv3.y));
                uint32_t p7 = h2u(__floats2half2_rn(xv3.z, xv3.w));
                asm volatile("st.shared.v4.b32 [%0], {%1,%2,%3,%4};"
                             :: "r"(dst + 16), "r"(p4), "r"(p5), "r"(p6), "r"(p7));
            }
            __syncthreads();                 // AF16[c&1] complete (barrier c-1 ordered
                                             // all MMA readers of this buffer)
            if (c + 1 < 36) ldg_chunk(c + 1);    // LDG hidden behind this chunk's MMAs

            const uint32_t aB = aF16lane + (c & 1) * AF16_BYTES;
            const uint2* bG  = B1g + (c % 12) * 4096;
            const uint2* bGn = bG + 4096;    // next chunk (valid when kc<11)

            #pragma unroll
            for (int j = 0; j < 4; j++) {
                uint32_t afr[4][4];
                #pragma unroll
                for (int mf = 0; mf < 4; mf++)
                    ldm_x4(afr[mf], aB + mf * 16 * AF16_STRIDE + j * 32);
                #pragma unroll
                for (int t = 0; t < 4; t++) {
                    uint32_t b0 = bv[j & 1][t].x, b1 = bv[j & 1][t].y;
                    // refill this ring slot at distance 2
                    if (j < 2)        bv[j & 1][t] = bG[(t * 4 + j + 2) * 32];
                    else if (kc < 11) bv[j & 1][t] = bGn[(t * 4 + (j - 2)) * 32];
                    mma16816(acc[0][t], afr[0], b0, b1);
                    mma16816(acc[1][t], afr[1], b0, b1);
                    mma16816(acc[2][t], afr[2], b0, b1);
                    mma16816(acc[3][t], afr[3], b0, b1);
                }
            }
            c++;
        }

        // preload layer-2 B j0+j1 EARLY (their L2 latency overlaps the whole
        // H1 store phase + barrier)
        uint2 bv2[2][2];
        #pragma unroll
        for (int t = 0; t < 2; t++) {
            bv2[0][t] = B2g[(t * 16 + 0) * 32];
            bv2[1][t] = B2g[(t * 16 + 1) * 32];
        }

        // ================= relu -> fp16 -> H1 smem (stride 528) =================
        #pragma unroll
        for (int mf = 0; mf < 4; mf++) {
            #pragma unroll
            for (int t = 0; t < 4; t++) {
                const int r0 = mf * 16 + (l >> 2);
                const int col = w * 32 + t * 8 + lq * 2;
                float* cc = acc[mf][t];
                *(uint32_t*)(smem + SM_H1 + r0 * 528 + col * 2) =
                    h2u(__floats2half2_rn(fmaxf(cc[0], 0.f), fmaxf(cc[1], 0.f)));
                *(uint32_t*)(smem + SM_H1 + (r0 + 8) * 528 + col * 2) =
                    h2u(__floats2half2_rn(fmaxf(cc[2], 0.f), fmaxf(cc[3], 0.f)));
            }
        }
        __syncthreads();

        // ================= layer 2: acc2[4 mf][2 t][4] = H1 @ W2^T ==============
        float acc2[4][2][4];
        #pragma unroll
        for (int a = 0; a < 4; a++)
            #pragma unroll
            for (int b = 0; b < 2; b++)
                #pragma unroll
                for (int q = 0; q < 4; q++) acc2[a][b][q] = 0.f;

        #pragma unroll
        for (int j = 0; j < 16; j++) {
            uint32_t afr[4][4];
            #pragma unroll
            for (int mf = 0; mf < 4; mf++)
                ldm_x4(afr[mf], h1base + mf * 16 * 528 + j * 32);
            #pragma unroll
            for (int t = 0; t < 2; t++) {
                uint32_t b0 = bv2[j & 1][t].x, b1 = bv2[j & 1][t].y;
                if (j < 14) bv2[j & 1][t] = B2g[(t * 16 + j + 2) * 32];
                mma16816(acc2[0][t], afr[0], b0, b1);
                mma16816(acc2[1][t], afr[1], b0, b1);
                mma16816(acc2[2][t], afr[2], b0, b1);
                mma16816(acc2[3][t], afr[3], b0, b1);
            }
        }
        // D-buffer accesses below: warp w owns cols [w*16, w*16+16) in all slices
        // -> no cross-warp race; H1 rewritten only after next slice's barriers.

        // ================= combine via D buffer (stride 272) ====================
        if (s == 0) {
            #pragma unroll
            for (int mf = 0; mf < 4; mf++)
                #pragma unroll
                for (int t = 0; t < 2; t++) {
                    const int r0 = mf * 16 + (l >> 2);
                    const int col = w * 16 + t * 8 + lq * 2;
                    float* cc = acc2[mf][t];
                    *(uint32_t*)(smem + SM_D + r0 * 272 + col * 2) =
                        h2u(__floats2half2_rn(fmaxf(cc[0], 0.f), fmaxf(cc[1], 0.f)));
                    *(uint32_t*)(smem + SM_D + (r0 + 8) * 272 + col * 2) =
                        h2u(__floats2half2_rn(fmaxf(cc[2], 0.f), fmaxf(cc[3], 0.f)));
                }
        } else if (s == 1) {
            #pragma unroll
            for (int mf = 0; mf < 4; mf++)
                #pragma unroll
                for (int t = 0; t < 2; t++) {
                    const int r0 = mf * 16 + (l >> 2);
                    const int col = w * 16 + t * 8 + lq * 2;
                    float* cc = acc2[mf][t];
                    uint32_t* d0 = (uint32_t*)(smem + SM_D + r0 * 272 + col * 2);
                    uint32_t* d1 = (uint32_t*)(smem + SM_D + (r0 + 8) * 272 + col * 2);
                    float2 fa = __half22float2(*(__half2*)d0);
                    float2 fb = __half22float2(*(__half2*)d1);
                    *d0 = h2u(__floats2half2_rn(fabsf(fa.x - fmaxf(cc[0], 0.f)),
                                                fabsf(fa.y - fmaxf(cc[1], 0.f))));
                    *d1 = h2u(__floats2half2_rn(fabsf(fb.x - fmaxf(cc[2], 0.f)),
                                                fabsf(fb.y - fmaxf(cc[3], 0.f))));
                }
        } else {
            // s==2: pd[mf][rr] = per-row partial over this warp's 16 cols
            float pd[4][2];
            #pragma unroll
            for (int mf = 0; mf < 4; mf++) { pd[mf][0] = 0.f; pd[mf][1] = 0.f; }
            #pragma unroll
            for (int mf = 0; mf < 4; mf++)
                #pragma unroll
                for (int t = 0; t < 2; t++) {
                    const int r0 = mf * 16 + (l >> 2);
                    const int col = w * 16 + t * 8 + lq * 2;
                    float* cc = acc2[mf][t];
                    float2 da = __half22float2(*(__half2*)(smem + SM_D + r0 * 272 + col * 2));
                    float2 db = __half22float2(*(__half2*)(smem + SM_D + (r0 + 8) * 272 + col * 2));
                    float w0 = W5s[col], w1 = W5s[col + 1];
                    pd[mf][0] += w0 * fmaxf(cc[0], 0.f) * da.x + w1 * fmaxf(cc[1], 0.f) * da.y;
                    pd[mf][1] += w0 * fmaxf(cc[2], 0.f) * db.x + w1 * fmaxf(cc[3], 0.f) * db.y;
                }
            #pragma unroll
            for (int mf = 0; mf < 4; mf++)
                #pragma unroll
                for (int rr = 0; rr < 2; rr++) {
                    float v = pd[mf][rr];
                    v += __shfl_xor_sync(0xFFFFFFFF, v, 1);
                    v += __shfl_xor_sync(0xFFFFFFFF, v, 2);
                    if (lq == 0) {
                        int row = mf * 16 + rr * 8 + (l >> 2);
                        parts[row * 8 + w] = v;      // warp w's 16-col partial
                    }
                }
        }
    }

    __syncthreads();
    if (tid < 64) {
        const float* p = parts + tid * 8;
        float sum = ((p[0] + p[1]) + (p[2] + p[3])) + ((p[4] + p[5]) + (p[6] + p[7]));
        out[blk * 64 + tid] = tanhf(fmaxf(sum, 0.f));
    }
}

// ------------------------------------------------------------------- launcher
extern "C" void kernel_launch(void* const* d_in, const int* in_sizes, int n_in,
                              void* d_out, int out_size) {
    const float* X  = (const float*)d_in[0];
    const float* W1 = (const float*)d_in[1];
    const float* W2 = (const float*)d_in[2];
    const float* W3 = (const float*)d_in[3];
    const float* W4 = (const float*)d_in[4];
    const float* W5 = (const float*)d_in[5];
    (void)in_sizes; (void)n_in; (void)out_size;

    cudaFuncSetAttribute(fused_kernel, cudaFuncAttributeMaxDynamicSharedMemorySize, SMEM_BYTES);

    prep_kernel<<<768, 256>>>(W1, W2, W3, W4);
    fused_kernel<<<1024, 256, SMEM_BYTES>>>(X, W5, (float*)d_out);
}